// round 16
// baseline (speedup 1.0000x reference)
#include <cuda_runtime.h>
#include <stdint.h>
#include <math.h>

#define NB 2048
#define ND 256
#define NDT 768
#define HSP 256                  // pair/triple hash slots
#define SBLK 256                 // stats blocks (8 rows each)
#define EBLK 1024                // entropy blocks (2 independent 128-thread groups, 1 row each)
#define TOTBLK (SBLK + EBLK)     // 1280
#define PW 2816                  // u32 words per row-table-set (11 KB)

// zero/static-initialized at module load; finish block resets them each run
__device__ double g_acc[8];      // [0]=mse sumsq, [1..7]=S1,S2,S3,S13,S23,S12,S123
__device__ double g_ck[14];      // ce,kl sums per 7 masks
__device__ unsigned int g_minbits[3] = {0xFFFFFFFFu, 0xFFFFFFFFu, 0xFFFFFFFFu};
__device__ unsigned int g_done;  // auto-wraps via atomicInc

__device__ __forceinline__ unsigned int fkey(float f) {
    unsigned int u = __float_as_uint(f);
    return (u & 0x80000000u) ? ~u : (u | 0x80000000u);
}
__device__ __forceinline__ float funkey(unsigned int u) {
    return __uint_as_float((u & 0x80000000u) ? (u & 0x7FFFFFFFu) : ~u);
}

// FMA-pipe exp (no MUFU)
__device__ __forceinline__ float fexp(float x) {
    float t = x * 1.44269504f;
    float fi = floorf(t);
    float f = t - fi;
    float p = 0.00134086f;
    p = fmaf(p, f, 0.00961812f);
    p = fmaf(p, f, 0.05550411f);
    p = fmaf(p, f, 0.24022651f);
    p = fmaf(p, f, 0.69314718f);
    p = fmaf(p, f, 1.0f);
    return __int_as_float(((int)fi + 127) << 23) * p;
}

// rank-contribution g(r) = r*log r - (r-1)*log(r-1); g(1)=0.
// Sum over inserts of g(rank) == sum over distinct values of c*log c (exact telescoping).
__device__ __forceinline__ float rank_contrib(uint32_t r) {
    float fr = (float)r, frm = (float)(r - 1u);
    return fr * __logf(fr) - ((r > 2u) ? frm * __logf(frm) : 0.f);
}

// ---------------- kernel 1: global mins of d1/d2/d3 ----------------
__global__ void min_kernel(const float* __restrict__ d1, const float* __restrict__ d2,
                           const float* __restrict__ d3) {
    __shared__ float smn[3][8];
    int tid = blockIdx.x * blockDim.x + threadIdx.x;   // grid 512*256 = 131072
    int lane = threadIdx.x & 31, w = threadIdx.x >> 5;
    const float4* a1 = (const float4*)d1;
    const float4* a2 = (const float4*)d2;
    const float4* a3 = (const float4*)d3;
    float4 v1 = a1[tid], v2 = a2[tid], v3 = a3[tid];   // 131072 f4 exactly
    float mn[3];
    mn[0] = fminf(fminf(v1.x, v1.y), fminf(v1.z, v1.w));
    mn[1] = fminf(fminf(v2.x, v2.y), fminf(v2.z, v2.w));
    mn[2] = fminf(fminf(v3.x, v3.y), fminf(v3.z, v3.w));
    for (int o = 16; o; o >>= 1)
#pragma unroll
        for (int k = 0; k < 3; k++) mn[k] = fminf(mn[k], __shfl_xor_sync(0xffffffffu, mn[k], o));
    if (lane == 0) { smn[0][w] = mn[0]; smn[1][w] = mn[1]; smn[2][w] = mn[2]; }
    __syncthreads();
    if (threadIdx.x == 0) {
        float m0 = smn[0][0], m1 = smn[1][0], m2 = smn[2][0];
        for (int i = 1; i < 8; i++) {
            m0 = fminf(m0, smn[0][i]); m1 = fminf(m1, smn[1][i]); m2 = fminf(m2, smn[2][i]);
        }
        atomicMin(&g_minbits[0], fkey(m0));
        atomicMin(&g_minbits[1], fkey(m1));
        atomicMin(&g_minbits[2], fkey(m2));
    }
}

// hash insert returning RANK (count after my insert); u32 packed: key<<9 | count
__device__ __forceinline__ uint32_t hinsert_rank8(uint32_t* table, uint32_t key) {
    uint32_t h = (key * 2654435769u) >> 24;
    uint32_t packed = (key << 9) | 1u;
    for (;;) {
        uint32_t old = atomicCAS(&table[h], 0u, packed);
        if (old == 0u) return 1u;
        if ((old >> 9) == key) { uint32_t prev = atomicAdd(&table[h], 1u); return (prev & 511u) + 1u; }
        h = (h + 1) & (HSP - 1);
    }
}
// u64 variant, key <= 33 bits
__device__ __forceinline__ uint32_t hinsert_rank64(unsigned long long* table, unsigned long long key) {
    uint32_t h = (uint32_t)((key * 0x9E3779B97F4A7C15ull) >> 56);
    unsigned long long packed = (key << 9) | 1ull;
    for (;;) {
        unsigned long long old = atomicCAS(&table[h], 0ull, packed);
        if (old == 0ull) return 1u;
        if ((old >> 9) == key) {
            unsigned long long prev = atomicAdd(&table[h], 1ull);
            return (uint32_t)(prev & 511ull) + 1u;
        }
        h = (h + 1) & (HSP - 1);
    }
}

// per-element finish: read single counts, pair/triple rank inserts, local contributions
// pool layout (u32 words): [0,1536) u8-packed singles, [1536,2304) pairs x3, [2304,2816) triple u64
__device__ __forceinline__ void entropy_finish(uint32_t* pool, uint32_t l1, uint32_t l2, uint32_t l3,
                                               float* A) {
    uint32_t c1 = (pool[0 * 512 + (l1 >> 2)] >> (8u * (l1 & 3u))) & 255u;
    uint32_t c2 = (pool[1 * 512 + (l2 >> 2)] >> (8u * (l2 & 3u))) & 255u;
    uint32_t c3 = (pool[2 * 512 + (l3 >> 2)] >> (8u * (l3 & 3u))) & 255u;
    if (c1 > 1u) A[0] += __logf((float)c1);
    if (c2 > 1u) A[1] += __logf((float)c2);
    if (c3 > 1u) A[2] += __logf((float)c3);
    uint32_t* ptab = pool + 1536;
    unsigned long long* ttab = (unsigned long long*)(pool + 2304);
    bool b1 = c1 > 1u, b2 = c2 > 1u, b3 = c3 > 1u;
    if (b1 & b3) {
        uint32_t r = hinsert_rank8(ptab + 0 * HSP, l1 | (l3 << 11));
        if (r > 1u) A[3] += rank_contrib(r);
    }
    if (b2 & b3) {
        uint32_t r = hinsert_rank8(ptab + 1 * HSP, l2 | (l3 << 11));
        if (r > 1u) A[4] += rank_contrib(r);
    }
    if (b1 & b2) {
        uint32_t r = hinsert_rank8(ptab + 2 * HSP, l1 | (l2 << 11));
        if (r > 1u) A[5] += rank_contrib(r);
        if (b3) {
            uint32_t rt = hinsert_rank64(ttab, (unsigned long long)l1 |
                                               ((unsigned long long)l2 << 11) |
                                               ((unsigned long long)l3 << 22));
            if (rt > 1u) A[6] += rank_contrib(rt);
        }
    }
}

#define GROUP_BAR(g) asm volatile("bar.sync %0, 128;" :: "r"(1 + (g)) : "memory")

// ---------------- mega kernel: stats blocks (0..255) + entropy blocks (256..1279) ----------------
// entropy block = TWO independent 128-thread groups (named barriers), one row each
__global__ void __launch_bounds__(256, 8) mega_kernel(
        const float* __restrict__ d1, const float* __restrict__ d2,
        const float* __restrict__ d3,
        const float* __restrict__ o1, const float* __restrict__ o2,
        const float* __restrict__ o3,
        const float* __restrict__ data, const float* __restrict__ outp,
        float* __restrict__ out) {
    __shared__ __align__(16) uint32_t pool[2 * PW];   // 22.5 KB (2 row-table-sets)
    __shared__ float ered[2 * 28];                    // per group: 7 subsets x 4 warps
    __shared__ float sstat[8][18];
    __shared__ double sacc[14];
    int bid = blockIdx.x, t = threadIdx.x;
    int lane = t & 31, w = t >> 5;

    if (bid < SBLK) {
        // ======== stats path: fused MSE slice + 8 rows (one warp per row) — champion code ========
        if (t < 14) sacc[t] = 0.0;
        {
            const float4* da = (const float4*)data;
            const float4* db = (const float4*)outp;
            float s = 0.f;
#pragma unroll
            for (int i = 0; i < 6; i++) {
                int idx = bid * 256 + t + i * 65536;
                float4 x = da[idx], y = db[idx];
                float q0 = x.x - y.x, q1 = x.y - y.y, q2 = x.z - y.z, q3 = x.w - y.w;
                s += q0 * q0 + q1 * q1 + q2 * q2 + q3 * q3;
            }
            for (int o = 16; o; o >>= 1) s += __shfl_xor_sync(0xffffffffu, s, o);
            if (lane == 0) atomicAdd(&g_acc[0], (double)s);
        }
        int gw8 = bid * 8 + w;
        const float* ds[3] = {d1, d2, d3};
        const float* os[3] = {o1, o2, o3};
#pragma unroll
        for (int k = 0; k < 3; k++) {
            const float* dp = ds[k] + gw8 * ND;
            const float* op = os[k] + gw8 * ND;
            // pass 1: maxes
            float mD = -INFINITY, mO = -INFINITY;
#pragma unroll
            for (int i = 0; i < 8; i++) {
                mD = fmaxf(mD, dp[lane + 32 * i]);
                mO = fmaxf(mO, op[lane + 32 * i]);
            }
            for (int o = 16; o; o >>= 1) {
                mD = fmaxf(mD, __shfl_xor_sync(0xffffffffu, mD, o));
                mO = fmaxf(mO, __shfl_xor_sync(0xffffffffu, mO, o));
            }
            // pass 2: exp sums (reload, L1-hot)
            float sD = 0.f, tO = 0.f, uD = 0.f, sO = 0.f;
#pragma unroll
            for (int i = 0; i < 8; i++) {
                float a = dp[lane + 32 * i], b = op[lane + 32 * i];
                float e = __expf(a - mD);       // MUFU
                sD += e; tO += e * b; uD += e * a;
                sO += fexp(b - mO);             // FMA
            }
            for (int o = 16; o; o >>= 1) {
                sD += __shfl_xor_sync(0xffffffffu, sD, o);
                tO += __shfl_xor_sync(0xffffffffu, tO, o);
                uD += __shfl_xor_sync(0xffffffffu, uD, o);
                sO += __shfl_xor_sync(0xffffffffu, sO, o);
            }
            if (lane == 0) {
                sstat[w][k * 6 + 0] = mD; sstat[w][k * 6 + 1] = sD;
                sstat[w][k * 6 + 2] = tO; sstat[w][k * 6 + 3] = uD;
                sstat[w][k * 6 + 4] = mO; sstat[w][k * 6 + 5] = sO;
            }
        }
        __syncthreads();
        // hsoft: 8 rows x 7 masks = 56 threads
        if (t < 56) {
            const int masks[7] = {1, 2, 4, 5, 6, 3, 7};
            int r = t / 7, j = t - r * 7;
            int m = masks[j];
            const float* st = sstat[r];
            float M = -INFINITY, MO = -INFINITY;
#pragma unroll
            for (int k = 0; k < 3; k++)
                if (m & (1 << k)) { M = fmaxf(M, st[k * 6 + 0]); MO = fmaxf(MO, st[k * 6 + 4]); }
            float S = 0.f, T = 0.f, U = 0.f, SO = 0.f;
#pragma unroll
            for (int k = 0; k < 3; k++)
                if (m & (1 << k)) {
                    float wt = __expf(st[k * 6 + 0] - M);
                    S += st[k * 6 + 1] * wt;
                    T += st[k * 6 + 2] * wt;
                    U += st[k * 6 + 3] * wt;
                    SO += st[k * 6 + 5] * __expf(st[k * 6 + 4] - MO);
                }
            float lseD = M + __logf(S);
            float lseO = MO + __logf(SO);
            float Spo = T / S, Spd = U / S;
            atomicAdd(&sacc[j], (double)(lseO - Spo));                      // ce
            atomicAdd(&sacc[7 + j], (double)((Spd - lseD) - (Spo - lseO))); // kl
        }
        __syncthreads();
        if (t < 14) atomicAdd(&g_ck[t], sacc[t]);
    } else {
        // ======== entropy path: two INDEPENDENT 128-thread groups, one row each ========
        int g = t >> 7;             // group 0 or 1
        int gt = t & 127;           // thread within group
        int gw = gt >> 5;           // warp within group (0..3)
        int row = (bid - SBLK) * 2 + g;
        int idxA = row * ND + gt;
        int idxB = idxA + 128;
        uint32_t* gp = pool + g * PW;

        // hoist loads (long latency overlapped with zeroing)
        float xa1 = d1[idxA], xa2 = d2[idxA], xa3 = d3[idxA];
        float xb1 = d1[idxB], xb2 = d2[idxB], xb3 = d3[idxB];

        // zero this group's pool: 704 uint4 over 128 threads; pre-zero ered
        {
            uint4* pz = (uint4*)gp;
#pragma unroll
            for (int i = 0; i < 5; i++) pz[gt + i * 128] = make_uint4(0, 0, 0, 0);
            if (gt < 64) pz[gt + 640] = make_uint4(0, 0, 0, 0);
            if (gt < 28) ered[g * 28 + gt] = 0.f;
        }

        float lo1 = floorf(funkey(g_minbits[0]));
        float lo2 = floorf(funkey(g_minbits[1]));
        float lo3 = floorf(funkey(g_minbits[2]));
        uint32_t l1a = (uint32_t)(int)floorf(__fdiv_rn(xa1 - lo1, 0.01f));
        uint32_t l2a = (uint32_t)(int)floorf(__fdiv_rn(xa2 - lo2, 0.01f));
        uint32_t l3a = (uint32_t)(int)floorf(__fdiv_rn(xa3 - lo3, 0.01f));
        uint32_t l1b = (uint32_t)(int)floorf(__fdiv_rn(xb1 - lo1, 0.01f));
        uint32_t l2b = (uint32_t)(int)floorf(__fdiv_rn(xb2 - lo2, 0.01f));
        uint32_t l3b = (uint32_t)(int)floorf(__fdiv_rn(xb3 - lo3, 0.01f));
        GROUP_BAR(g);

        // singles: 6 fire-and-forget RED into u8-packed bins
        atomicAdd(&gp[0 * 512 + (l1a >> 2)], 1u << (8u * (l1a & 3u)));
        atomicAdd(&gp[1 * 512 + (l2a >> 2)], 1u << (8u * (l2a & 3u)));
        atomicAdd(&gp[2 * 512 + (l3a >> 2)], 1u << (8u * (l3a & 3u)));
        atomicAdd(&gp[0 * 512 + (l1b >> 2)], 1u << (8u * (l1b & 3u)));
        atomicAdd(&gp[1 * 512 + (l2b >> 2)], 1u << (8u * (l2b & 3u)));
        atomicAdd(&gp[2 * 512 + (l3b >> 2)], 1u << (8u * (l3b & 3u)));
        GROUP_BAR(g);

        // counts + pair/triple rank inserts (no further table barrier)
        float A[7] = {0.f, 0.f, 0.f, 0.f, 0.f, 0.f, 0.f};
        entropy_finish(gp, l1a, l2a, l3a, A);
        entropy_finish(gp, l1b, l2b, l3b, A);

        // reduce 7 sums across this group's 4 warps
#pragma unroll
        for (int k = 0; k < 3; k++) {
            float x = A[k];
            for (int o = 16; o; o >>= 1) x += __shfl_xor_sync(0xffffffffu, x, o);
            if (lane == 0) ered[g * 28 + k * 4 + gw] = x;
        }
#pragma unroll
        for (int k = 3; k < 7; k++) {
            unsigned int b = __ballot_sync(0xffffffffu, A[k] != 0.f);
            if (b) {
                float x = A[k];
                for (int o = 16; o; o >>= 1) x += __shfl_xor_sync(0xffffffffu, x, o);
                if (lane == 0) ered[g * 28 + k * 4 + gw] = x;
            }
        }
        GROUP_BAR(g);
        if (gt < 7) {
            double a = 0.0;
#pragma unroll
            for (int i = 0; i < 4; i++) a += (double)ered[g * 28 + gt * 4 + i];
            // row entropy H = log(256) - A/256
            atomicAdd(&g_acc[1 + gt], 5.545177444479562 - a * (1.0 / 256.0));
        }
    }

    // ======== last block: assemble scalar + reset state for next replay ========
    __syncthreads();
    if (t == 0) {
        __threadfence();
        unsigned int old = atomicInc(&g_done, TOTBLK - 1);   // wraps to 0 on last
        if (old == TOTBLK - 1) {
            const int masks[7] = {1, 2, 4, 5, 6, 3, 7};
            double Hout[7];
            for (int s = 0; s < 7; s++) {
                int C = ND * __popc(masks[s]);
                Hout[s] = g_ck[s] / (double)NB - g_ck[7 + s] / ((double)NB * (double)C);
            }
            double Hd1 = g_acc[1] / NB, Hd2 = g_acc[2] / NB, Hd3 = g_acc[3] / NB;
            double Hin13 = g_acc[4] / NB, Hin23 = g_acc[5] / NB, Hin12 = g_acc[6] / NB;
            double H1 = Hd1 - Hout[0];
            double H2 = Hd2 - Hout[1];
            double H3 = Hd3 - Hout[2];
            double data13 = Hd1 + Hd3 - Hin13;
            double data23 = Hd2 + Hd3 - Hin23;
            double data12 = Hd1 + Hd2 - Hin12;
            double lab13 = Hout[0] + Hout[2] - Hout[3];
            double lab23 = Hout[1] + Hout[2] - Hout[4];
            double lab12 = Hout[0] + Hout[1] - Hout[5];
            double MI13 = lab13 - data13, MI23 = lab23 - data23, MI12 = lab12 - data12;
            double aveDataCMI = g_acc[4] + g_acc[5] - g_acc[3] - g_acc[7];
            double aveLabCMI = Hout[4] - Hout[2] + Hout[3] - Hout[6];
            double CMI = aveLabCMI - aveDataCMI;
            double mse = 0.5 * (g_acc[0] / ((double)NB * (double)NDT));
            double loss = 0.5 * mse
                        + 0.25 * (H1 * H1 + H2 * H2 + H3 * H3)
                        + 0.25 * (MI13 * MI13 + MI23 * MI23 + MI12 * MI12 + CMI * CMI);
            out[0] = (float)loss;
            // reset for next graph replay
            for (int i = 0; i < 8; i++) g_acc[i] = 0.0;
            for (int i = 0; i < 14; i++) g_ck[i] = 0.0;
            g_minbits[0] = 0xFFFFFFFFu; g_minbits[1] = 0xFFFFFFFFu; g_minbits[2] = 0xFFFFFFFFu;
        }
    }
}

extern "C" void kernel_launch(void* const* d_in, const int* in_sizes, int n_in,
                              void* d_out, int out_size) {
    (void)in_sizes; (void)n_in; (void)out_size;
    const float* data  = (const float*)d_in[0];
    const float* data1 = (const float*)d_in[1];
    const float* data2 = (const float*)d_in[2];
    const float* data3 = (const float*)d_in[3];
    const float* out1  = (const float*)d_in[4];
    const float* out2  = (const float*)d_in[5];
    const float* out3  = (const float*)d_in[6];
    const float* outp  = (const float*)d_in[7];

    min_kernel<<<512, 256>>>(data1, data2, data3);
    mega_kernel<<<TOTBLK, 256>>>(data1, data2, data3, out1, out2, out3, data, outp, (float*)d_out);
}

// round 17
// speedup vs baseline: 1.2554x; 1.2554x over previous
#include <cuda_runtime.h>
#include <stdint.h>
#include <math.h>

#define NB 2048
#define ND 256
#define NDT 768
#define HSP 256                  // pair/triple hash slots
#define SBLK 256                 // stats blocks (8 rows each)
#define TOTBLK (NB + SBLK)

// zero/static-initialized at module load; finish block resets them each run
__device__ double g_acc[8];      // [0]=mse sumsq, [1..7]=S1,S2,S3,S13,S23,S12,S123
__device__ double g_ck[14];      // ce,kl sums per 7 masks
__device__ unsigned int g_minbits[3] = {0xFFFFFFFFu, 0xFFFFFFFFu, 0xFFFFFFFFu};
__device__ unsigned int g_done;  // auto-wraps via atomicInc

__device__ __forceinline__ unsigned int fkey(float f) {
    unsigned int u = __float_as_uint(f);
    return (u & 0x80000000u) ? ~u : (u | 0x80000000u);
}
__device__ __forceinline__ float funkey(unsigned int u) {
    return __uint_as_float((u & 0x80000000u) ? (u & 0x7FFFFFFFu) : ~u);
}

// FMA-pipe exp (no MUFU)
__device__ __forceinline__ float fexp(float x) {
    float t = x * 1.44269504f;
    float fi = floorf(t);
    float f = t - fi;
    float p = 0.00134086f;
    p = fmaf(p, f, 0.00961812f);
    p = fmaf(p, f, 0.05550411f);
    p = fmaf(p, f, 0.24022651f);
    p = fmaf(p, f, 0.69314718f);
    p = fmaf(p, f, 1.0f);
    return __int_as_float(((int)fi + 127) << 23) * p;
}

// ---------------- kernel 1: global mins of d1/d2/d3 ----------------
__global__ void min_kernel(const float* __restrict__ d1, const float* __restrict__ d2,
                           const float* __restrict__ d3) {
    __shared__ float smn[3][8];
    int tid = blockIdx.x * blockDim.x + threadIdx.x;   // grid 512*256 = 131072
    int lane = threadIdx.x & 31, w = threadIdx.x >> 5;
    const float4* a1 = (const float4*)d1;
    const float4* a2 = (const float4*)d2;
    const float4* a3 = (const float4*)d3;
    float4 v1 = a1[tid], v2 = a2[tid], v3 = a3[tid];   // 131072 f4 exactly
    float mn[3];
    mn[0] = fminf(fminf(v1.x, v1.y), fminf(v1.z, v1.w));
    mn[1] = fminf(fminf(v2.x, v2.y), fminf(v2.z, v2.w));
    mn[2] = fminf(fminf(v3.x, v3.y), fminf(v3.z, v3.w));
    for (int o = 16; o; o >>= 1)
#pragma unroll
        for (int k = 0; k < 3; k++) mn[k] = fminf(mn[k], __shfl_xor_sync(0xffffffffu, mn[k], o));
    if (lane == 0) { smn[0][w] = mn[0]; smn[1][w] = mn[1]; smn[2][w] = mn[2]; }
    __syncthreads();
    if (threadIdx.x == 0) {
        float m0 = smn[0][0], m1 = smn[1][0], m2 = smn[2][0];
        for (int i = 1; i < 8; i++) {
            m0 = fminf(m0, smn[0][i]); m1 = fminf(m1, smn[1][i]); m2 = fminf(m2, smn[2][i]);
        }
        atomicMin(&g_minbits[0], fkey(m0));
        atomicMin(&g_minbits[1], fkey(m1));
        atomicMin(&g_minbits[2], fkey(m2));
    }
}

// packed-slot insert (u32, 256 slots): word = key<<9 | count, key <= 22 bits; returns slot
__device__ __forceinline__ uint32_t hinsert8(uint32_t* table, uint32_t key) {
    uint32_t h = (key * 2654435769u) >> 24;
    uint32_t packed = (key << 9) | 1u;
    for (;;) {
        uint32_t old = atomicCAS(&table[h], 0u, packed);
        if (old == 0u) return h;
        if ((old >> 9) == key) { atomicAdd(&table[h], 1u); return h; }
        h = (h + 1) & (HSP - 1);
    }
}
// packed-slot insert (u64, 256 slots): word = key<<9 | count, key <= 33 bits; returns slot
__device__ __forceinline__ uint32_t hinsert64(unsigned long long* table, unsigned long long key) {
    uint32_t h = (uint32_t)((key * 0x9E3779B97F4A7C15ull) >> 56);
    unsigned long long packed = (key << 9) | 1ull;
    for (;;) {
        unsigned long long old = atomicCAS(&table[h], 0ull, packed);
        if (old == 0ull) return h;
        if ((old >> 9) == key) { atomicAdd(&table[h], 1ull); return h; }
        h = (h + 1) & (HSP - 1);
    }
}

// ---------------- mega kernel: stats blocks (0..255) + entropy blocks (256..2303) ----------------
// pool layout (u32 words): [0,1536) u8-packed single counts (3 vars x 512 words x 4 bins)
//                          [1536,2304) pair tables (3 x 256)
//                          [2304,2816) triple table (256 x u64)
__global__ void __launch_bounds__(256, 8) mega_kernel(
        const float* __restrict__ d1, const float* __restrict__ d2,
        const float* __restrict__ d3,
        const float* __restrict__ o1, const float* __restrict__ o2,
        const float* __restrict__ o3,
        const float* __restrict__ data, const float* __restrict__ outp,
        float* __restrict__ out) {
    __shared__ __align__(16) uint32_t pool[2816];   // 11 KB
    __shared__ float ered[7 * 8];
    __shared__ float sstat[8][18];
    __shared__ double sacc[14];
    int bid = blockIdx.x, t = threadIdx.x;
    int lane = t & 31, w = t >> 5;

    if (bid < SBLK) {
        // ======== stats path: fused MSE slice + 8 rows (one warp per row) ========
        if (t < 14) sacc[t] = 0.0;
        {
            const float4* da = (const float4*)data;
            const float4* db = (const float4*)outp;
            float s = 0.f;
#pragma unroll
            for (int i = 0; i < 6; i++) {
                int idx = bid * 256 + t + i * 65536;
                float4 x = da[idx], y = db[idx];
                float q0 = x.x - y.x, q1 = x.y - y.y, q2 = x.z - y.z, q3 = x.w - y.w;
                s += q0 * q0 + q1 * q1 + q2 * q2 + q3 * q3;
            }
            for (int o = 16; o; o >>= 1) s += __shfl_xor_sync(0xffffffffu, s, o);
            if (lane == 0) atomicAdd(&g_acc[0], (double)s);
        }
        int gw = bid * 8 + w;
        const float* ds[3] = {d1, d2, d3};
        const float* os[3] = {o1, o2, o3};
#pragma unroll
        for (int k = 0; k < 3; k++) {
            const float* dp = ds[k] + gw * ND;
            const float* op = os[k] + gw * ND;
            // pass 1: maxes
            float mD = -INFINITY, mO = -INFINITY;
#pragma unroll
            for (int i = 0; i < 8; i++) {
                mD = fmaxf(mD, dp[lane + 32 * i]);
                mO = fmaxf(mO, op[lane + 32 * i]);
            }
            for (int o = 16; o; o >>= 1) {
                mD = fmaxf(mD, __shfl_xor_sync(0xffffffffu, mD, o));
                mO = fmaxf(mO, __shfl_xor_sync(0xffffffffu, mO, o));
            }
            // pass 2: exp sums (reload, L1-hot)
            float sD = 0.f, tO = 0.f, uD = 0.f, sO = 0.f;
#pragma unroll
            for (int i = 0; i < 8; i++) {
                float a = dp[lane + 32 * i], b = op[lane + 32 * i];
                float e = __expf(a - mD);       // MUFU
                sD += e; tO += e * b; uD += e * a;
                sO += fexp(b - mO);             // FMA
            }
            for (int o = 16; o; o >>= 1) {
                sD += __shfl_xor_sync(0xffffffffu, sD, o);
                tO += __shfl_xor_sync(0xffffffffu, tO, o);
                uD += __shfl_xor_sync(0xffffffffu, uD, o);
                sO += __shfl_xor_sync(0xffffffffu, sO, o);
            }
            if (lane == 0) {
                sstat[w][k * 6 + 0] = mD; sstat[w][k * 6 + 1] = sD;
                sstat[w][k * 6 + 2] = tO; sstat[w][k * 6 + 3] = uD;
                sstat[w][k * 6 + 4] = mO; sstat[w][k * 6 + 5] = sO;
            }
        }
        __syncthreads();
        // hsoft: 8 rows x 7 masks = 56 threads
        if (t < 56) {
            const int masks[7] = {1, 2, 4, 5, 6, 3, 7};
            int r = t / 7, j = t - r * 7;
            int m = masks[j];
            const float* st = sstat[r];
            float M = -INFINITY, MO = -INFINITY;
#pragma unroll
            for (int k = 0; k < 3; k++)
                if (m & (1 << k)) { M = fmaxf(M, st[k * 6 + 0]); MO = fmaxf(MO, st[k * 6 + 4]); }
            float S = 0.f, T = 0.f, U = 0.f, SO = 0.f;
#pragma unroll
            for (int k = 0; k < 3; k++)
                if (m & (1 << k)) {
                    float wt = __expf(st[k * 6 + 0] - M);
                    S += st[k * 6 + 1] * wt;
                    T += st[k * 6 + 2] * wt;
                    U += st[k * 6 + 3] * wt;
                    SO += st[k * 6 + 5] * __expf(st[k * 6 + 4] - MO);
                }
            float lseD = M + __logf(S);
            float lseO = MO + __logf(SO);
            float Spo = T / S, Spd = U / S;
            atomicAdd(&sacc[j], (double)(lseO - Spo));                      // ce
            atomicAdd(&sacc[7 + j], (double)((Spd - lseD) - (Spo - lseO))); // kl
        }
        __syncthreads();
        if (t < 14) atomicAdd(&g_ck[t], sacc[t]);
    } else {
        // ======== entropy path: one row ========
        int row = bid - SBLK;
        int idx = row * ND + t;
        float lo1 = floorf(funkey(g_minbits[0]));
        float lo2 = floorf(funkey(g_minbits[1]));
        float lo3 = floorf(funkey(g_minbits[2]));
        uint32_t l1 = (uint32_t)(int)floorf(__fdiv_rn(d1[idx] - lo1, 0.01f));
        uint32_t l2 = (uint32_t)(int)floorf(__fdiv_rn(d2[idx] - lo2, 0.01f));
        uint32_t l3 = (uint32_t)(int)floorf(__fdiv_rn(d3[idx] - lo3, 0.01f));

        // zero pool: 704 uint4
        {
            uint4* pz = (uint4*)pool;
            pz[t] = make_uint4(0, 0, 0, 0);
            pz[t + 256] = make_uint4(0, 0, 0, 0);
            if (t < 192) pz[t + 512] = make_uint4(0, 0, 0, 0);
        }
        __syncthreads();

        // singles: one plain atomicAdd each into u8-packed bins
        atomicAdd(&pool[0 * 512 + (l1 >> 2)], 1u << (8u * (l1 & 3u)));
        atomicAdd(&pool[1 * 512 + (l2 >> 2)], 1u << (8u * (l2 & 3u)));
        atomicAdd(&pool[2 * 512 + (l3 >> 2)], 1u << (8u * (l3 & 3u)));
        __syncthreads();

        uint32_t c1 = (pool[0 * 512 + (l1 >> 2)] >> (8u * (l1 & 3u))) & 255u;
        uint32_t c2 = (pool[1 * 512 + (l2 >> 2)] >> (8u * (l2 & 3u))) & 255u;
        uint32_t c3 = (pool[2 * 512 + (l3 >> 2)] >> (8u * (l3 & 3u))) & 255u;

        // pairs + triple in ONE round (singles-only pruning)
        uint32_t* ptab = pool + 1536;
        unsigned long long* ttab = (unsigned long long*)(pool + 2304);
        bool a13 = (c1 > 1u) & (c3 > 1u);
        bool a23 = (c2 > 1u) & (c3 > 1u);
        bool a12 = (c1 > 1u) & (c2 > 1u);
        bool a123 = a12 & (c3 > 1u);
        uint32_t h13 = 0, h23 = 0, h12 = 0, h123 = 0;
        if (a13) h13 = hinsert8(ptab + 0 * HSP, l1 | (l3 << 11));
        if (a23) h23 = hinsert8(ptab + 1 * HSP, l2 | (l3 << 11));
        if (a12) h12 = hinsert8(ptab + 2 * HSP, l1 | (l2 << 11));
        if (a123) h123 = hinsert64(ttab, (unsigned long long)l1 |
                                         ((unsigned long long)l2 << 11) |
                                         ((unsigned long long)l3 << 22));
        __syncthreads();

        uint32_t c13 = a13 ? (ptab[0 * HSP + h13] & 511u) : 1u;
        uint32_t c23 = a23 ? (ptab[1 * HSP + h23] & 511u) : 1u;
        uint32_t c12 = a12 ? (ptab[2 * HSP + h12] & 511u) : 1u;
        uint32_t c123 = a123 ? (uint32_t)(ttab[h123] & 511ull) : 1u;

        float A[7];
        A[0] = (c1 > 1u) ? __logf((float)c1) : 0.f;
        A[1] = (c2 > 1u) ? __logf((float)c2) : 0.f;
        A[2] = (c3 > 1u) ? __logf((float)c3) : 0.f;
        A[3] = (c13 > 1u) ? __logf((float)c13) : 0.f;
        A[4] = (c23 > 1u) ? __logf((float)c23) : 0.f;
        A[5] = (c12 > 1u) ? __logf((float)c12) : 0.f;
        A[6] = (c123 > 1u) ? __logf((float)c123) : 0.f;

        // dense reductions for singles (always nonzero somewhere)
#pragma unroll
        for (int k = 0; k < 3; k++) {
            float x = A[k];
            for (int o = 16; o; o >>= 1) x += __shfl_xor_sync(0xffffffffu, x, o);
            if (lane == 0) ered[k * 8 + w] = x;
        }
        // ballot-skip reductions for pairs/triple (~3% participation)
#pragma unroll
        for (int k = 3; k < 7; k++) {
            unsigned int b = __ballot_sync(0xffffffffu, A[k] != 0.f);
            if (b) {
                float x = A[k];
                for (int o = 16; o; o >>= 1) x += __shfl_xor_sync(0xffffffffu, x, o);
                if (lane == 0) ered[k * 8 + w] = x;
            } else if (lane == 0) {
                ered[k * 8 + w] = 0.f;
            }
        }
        __syncthreads();
        if (t < 7) {
            double a = 0.0;
#pragma unroll
            for (int i = 0; i < 8; i++) a += (double)ered[t * 8 + i];
            // row entropy H = log(256) - A/256
            atomicAdd(&g_acc[1 + t], 5.545177444479562 - a * (1.0 / 256.0));
        }
    }

    // ======== last block: assemble scalar + reset state for next replay ========
    __syncthreads();
    if (t == 0) {
        __threadfence();
        unsigned int old = atomicInc(&g_done, TOTBLK - 1);   // wraps to 0 on last
        if (old == TOTBLK - 1) {
            const int masks[7] = {1, 2, 4, 5, 6, 3, 7};
            double Hout[7];
            for (int s = 0; s < 7; s++) {
                int C = ND * __popc(masks[s]);
                Hout[s] = g_ck[s] / (double)NB - g_ck[7 + s] / ((double)NB * (double)C);
            }
            double Hd1 = g_acc[1] / NB, Hd2 = g_acc[2] / NB, Hd3 = g_acc[3] / NB;
            double Hin13 = g_acc[4] / NB, Hin23 = g_acc[5] / NB, Hin12 = g_acc[6] / NB;
            double H1 = Hd1 - Hout[0];
            double H2 = Hd2 - Hout[1];
            double H3 = Hd3 - Hout[2];
            double data13 = Hd1 + Hd3 - Hin13;
            double data23 = Hd2 + Hd3 - Hin23;
            double data12 = Hd1 + Hd2 - Hin12;
            double lab13 = Hout[0] + Hout[2] - Hout[3];
            double lab23 = Hout[1] + Hout[2] - Hout[4];
            double lab12 = Hout[0] + Hout[1] - Hout[5];
            double MI13 = lab13 - data13, MI23 = lab23 - data23, MI12 = lab12 - data12;
            double aveDataCMI = g_acc[4] + g_acc[5] - g_acc[3] - g_acc[7];
            double aveLabCMI = Hout[4] - Hout[2] + Hout[3] - Hout[6];
            double CMI = aveLabCMI - aveDataCMI;
            double mse = 0.5 * (g_acc[0] / ((double)NB * (double)NDT));
            double loss = 0.5 * mse
                        + 0.25 * (H1 * H1 + H2 * H2 + H3 * H3)
                        + 0.25 * (MI13 * MI13 + MI23 * MI23 + MI12 * MI12 + CMI * CMI);
            out[0] = (float)loss;
            // reset for next graph replay
            for (int i = 0; i < 8; i++) g_acc[i] = 0.0;
            for (int i = 0; i < 14; i++) g_ck[i] = 0.0;
            g_minbits[0] = 0xFFFFFFFFu; g_minbits[1] = 0xFFFFFFFFu; g_minbits[2] = 0xFFFFFFFFu;
        }
    }
}

extern "C" void kernel_launch(void* const* d_in, const int* in_sizes, int n_in,
                              void* d_out, int out_size) {
    (void)in_sizes; (void)n_in; (void)out_size;
    const float* data  = (const float*)d_in[0];
    const float* data1 = (const float*)d_in[1];
    const float* data2 = (const float*)d_in[2];
    const float* data3 = (const float*)d_in[3];
    const float* out1  = (const float*)d_in[4];
    const float* out2  = (const float*)d_in[5];
    const float* out3  = (const float*)d_in[6];
    const float* outp  = (const float*)d_in[7];

    min_kernel<<<512, 256>>>(data1, data2, data3);
    mega_kernel<<<TOTBLK, 256>>>(data1, data2, data3, out1, out2, out3, data, outp, (float*)d_out);
}